// round 5
// baseline (speedup 1.0000x reference)
#include <cuda_runtime.h>
#include <cstdint>

#define FULLMASK 0xFFFFFFFFu
#define AR_P    48
#define TLEN    168          // forecast length
#define HIST    336
#define TPB     128

// W row-major: g_W[t*48 + j] = W[t][j];  g_d[t] = mu*(1 - rowsum_t) + sigma*c_t
__device__ float g_W[TLEN * AR_P];
__device__ float g_d[TLEN];

// ---------------------------------------------------------------------------
// Kernel 1: one warp builds W (row-major) and the affine offsets d via the
// companion rank-1 shift recursion:
//   W[0] = phi;  W[t][j] = W[t-1][j-1] + W[t-1][47]*phi[j]
//   c[t] = bias * (1 + sum_{u<t} W[u][47])
//   d[t] = mu*(1 - sum_j W[t][j]) + sigma*c[t]
// so that out_t = sum_j W[t][j]*y_j + d[t]  (no standardization needed).
// Lanes hold column j=l in va; lanes 0..15 also hold j=l+32 in vb.
// ---------------------------------------------------------------------------
__global__ void build_w_kernel(const float* __restrict__ phi,
                               const float* __restrict__ bias,
                               const float* __restrict__ mu_p,
                               const float* __restrict__ sigma_p) {
    const int l = threadIdx.x;
    const float pa = phi[l];
    const float pb = (l < 16) ? phi[l + 32] : 0.0f;
    float va = pa;
    float vb = pb;
    const float b0 = bias[0];
    const float mu = mu_p[0];
    const float sigma = sigma_p[0];
    float acc = 1.0f;

    for (int t = 0; t < TLEN; ++t) {
        g_W[t * AR_P + l] = va;
        if (l < 16) g_W[t * AR_P + 32 + l] = vb;

        // rowsum across all 48 coefficients
        float rs = va + ((l < 16) ? vb : 0.0f);
#pragma unroll
        for (int o = 16; o; o >>= 1) rs += __shfl_xor_sync(FULLMASK, rs, o);
        if (l == 0) g_d[t] = mu * (1.0f - rs) + sigma * (b0 * acc);

        const float v47 = __shfl_sync(FULLMASK, vb, 15);   // W[t][47]
        acc += v47;

        float sa = __shfl_up_sync(FULLMASK, va, 1);        // shift: v[l-1]
        const float a31 = __shfl_sync(FULLMASK, va, 31);
        float sb = __shfl_up_sync(FULLMASK, vb, 1);
        if (l == 0) { sa = 0.0f; sb = a31; }

        va = fmaf(v47, pa, sa);
        vb = fmaf(v47, pb, sb);
    }
}

// ---------------------------------------------------------------------------
// Packed fp32x2 helpers (Blackwell fma.rn.f32x2)
// ---------------------------------------------------------------------------
__device__ __forceinline__ unsigned long long pk2(float x, float y) {
    unsigned long long r;
    asm("mov.b64 %0, {%1, %2};" : "=l"(r) : "f"(x), "f"(y));
    return r;
}
__device__ __forceinline__ unsigned long long fma2(unsigned long long a,
                                                   unsigned long long b,
                                                   unsigned long long c) {
    unsigned long long d;
    asm("fma.rn.f32x2 %0, %1, %2, %3;" : "=l"(d) : "l"(a), "l"(b), "l"(c));
    return d;
}
__device__ __forceinline__ float2 up2(unsigned long long v) {
    float2 f;
    asm("mov.b64 {%0, %1}, %2;" : "=f"(f.x), "=f"(f.y) : "l"(v));
    return f;
}

// ---------------------------------------------------------------------------
// Kernel 2: one series per thread.
//   state: 24 u64 = raw adjacent-j pairs of the last 48 history values (48 regs,
//          no spill, zero prologue arithmetic).
//   per t: 24 FMA2 over j-pairs (even/odd partial sums), result = acc.x+acc.y,
//          seeded with the affine offset d[t].
//   W rows broadcast from shared via LDS.128 (conflict-free, N=1).
//   Each thread also writes its logvar row (constant) — no separate fill blocks.
// ---------------------------------------------------------------------------
__global__ void __launch_bounds__(TPB, 6)
forecast_kernel(const float* __restrict__ enc_l,
                const float* __restrict__ sigma_p,
                const float* __restrict__ ls2_p,
                float* __restrict__ out,
                int B) {
    __shared__ float sW[TLEN * AR_P];   // 31.5 KB row-major
    __shared__ float sd[TLEN];

    const int tid = threadIdx.x;
    {
        const float4* src4 = reinterpret_cast<const float4*>(g_W);
        float4* dst4 = reinterpret_cast<float4*>(sW);
        for (int i = tid; i < (TLEN * AR_P) / 4; i += TPB) dst4[i] = src4[i];
        for (int i = tid; i < TLEN; i += TPB) sd[i] = g_d[i];
    }
    __syncthreads();

    const int b = blockIdx.x * TPB + tid;
    if (b >= B) return;

    // Raw history pairs: s2[q] = (y[2q], y[2q+1]) — pure 16B copies.
    unsigned long long s2[AR_P / 2];
    {
        const ulonglong2* src = reinterpret_cast<const ulonglong2*>(
            enc_l + (size_t)b * HIST + (HIST - AR_P));
#pragma unroll
        for (int q = 0; q < AR_P / 4; ++q) {
            const ulonglong2 v = src[q];
            s2[2 * q + 0] = v.x;
            s2[2 * q + 1] = v.y;
        }
    }

    float* orow = out + (size_t)b * TLEN;

#pragma unroll 1
    for (int t4 = 0; t4 < TLEN / 4; ++t4) {
        const float4 dq = *reinterpret_cast<const float4*>(sd + 4 * t4);
        float res[4];
#pragma unroll
        for (int t = 0; t < 4; ++t) {
            const ulonglong2* wr = reinterpret_cast<const ulonglong2*>(
                sW + (4 * t4 + t) * AR_P);
            const float dt = (t == 0) ? dq.x : (t == 1) ? dq.y
                           : (t == 2) ? dq.z : dq.w;
            unsigned long long a0 = pk2(dt, 0.0f);
            unsigned long long a1 = pk2(0.0f, 0.0f);
#pragma unroll
            for (int q = 0; q < AR_P / 8; ++q) {        // 6 iters, 2 LDS.128 each
                const ulonglong2 w0 = wr[2 * q + 0];
                const ulonglong2 w1 = wr[2 * q + 1];
                a0 = fma2(w0.x, s2[4 * q + 0], a0);
                a1 = fma2(w0.y, s2[4 * q + 1], a1);
                a0 = fma2(w1.x, s2[4 * q + 2], a0);
                a1 = fma2(w1.y, s2[4 * q + 3], a1);
            }
            const float2 f0 = up2(a0);
            const float2 f1 = up2(a1);
            res[t] = (f0.x + f1.x) + (f0.y + f1.y);
        }
        float4 o; o.x = res[0]; o.y = res[1]; o.z = res[2]; o.w = res[3];
        *reinterpret_cast<float4*>(orow + 4 * t4) = o;
    }

    // logvar row: constant broadcast
    const float L = ls2_p[0] + 2.0f * logf(sigma_p[0]);
    float4 Lv; Lv.x = L; Lv.y = L; Lv.z = L; Lv.w = L;
    float4* lrow = reinterpret_cast<float4*>(out + (size_t)B * TLEN + (size_t)b * TLEN);
#pragma unroll 1
    for (int t4 = 0; t4 < TLEN / 4; ++t4) lrow[t4] = Lv;
}

// ---------------------------------------------------------------------------
extern "C" void kernel_launch(void* const* d_in, const int* in_sizes, int n_in,
                              void* d_out, int out_size) {
    // inputs: enc_l, enc_t, enc_w, enc_s, phi, bias, log_sigma2, mu, sigma
    const float* enc_l = (const float*)d_in[0];
    const float* phi   = (const float*)d_in[4];
    const float* bias  = (const float*)d_in[5];
    const float* ls2   = (const float*)d_in[6];
    const float* mu    = (const float*)d_in[7];
    const float* sigma = (const float*)d_in[8];
    float* out = (float*)d_out;

    const int B = in_sizes[0] / HIST;   // enc_l is (B, HIST, 1)

    build_w_kernel<<<1, 32>>>(phi, bias, mu, sigma);

    const int blocks = (B + TPB - 1) / TPB;
    forecast_kernel<<<blocks, TPB>>>(enc_l, sigma, ls2, out, B);
}

// round 7
// speedup vs baseline: 1.7592x; 1.7592x over previous
#include <cuda_runtime.h>
#include <cstdint>

#define FULLMASK 0xFFFFFFFFu
#define AR_P    48
#define TLEN    168          // forecast length
#define HIST    336
#define TPB     96
#define SPT     2            // series per thread (register-resident states)
#define SPB     (TPB * SPT)  // 192 series per block

// W transposed: g_WT[j*TLEN + t] = W[t][j]
// g_d[t] = mu*(1 - rowsum_t) + sigma*c_t   (affine offset: out_t = W[t]·y + d_t)
__device__ float g_WT[AR_P * TLEN];
__device__ float g_d[TLEN];

// ---------------------------------------------------------------------------
// Kernel 1: one warp builds WT and d via the companion rank-1 shift recursion:
//   W[0] = phi;  W[t][j] = W[t-1][j-1] + W[t-1][47]*phi[j]
//   c[t] = bias * (1 + sum_{u<t} W[u][47])
//   d[t] = mu*(1 - sum_j W[t][j]) + sigma*c[t]
// ---------------------------------------------------------------------------
__global__ void build_w_kernel(const float* __restrict__ phi,
                               const float* __restrict__ bias,
                               const float* __restrict__ mu_p,
                               const float* __restrict__ sigma_p) {
    const int l = threadIdx.x;
    const float pa = phi[l];
    const float pb = (l < 16) ? phi[l + 32] : 0.0f;
    float va = pa;
    float vb = pb;
    const float b0 = bias[0];
    const float mu = mu_p[0];
    const float sigma = sigma_p[0];
    float acc = 1.0f;

    for (int t = 0; t < TLEN; ++t) {
        g_WT[l * TLEN + t] = va;
        if (l < 16) g_WT[(l + 32) * TLEN + t] = vb;

        float rs = va + ((l < 16) ? vb : 0.0f);
#pragma unroll
        for (int o = 16; o; o >>= 1) rs += __shfl_xor_sync(FULLMASK, rs, o);
        if (l == 0) g_d[t] = mu * (1.0f - rs) + sigma * (b0 * acc);

        const float v47 = __shfl_sync(FULLMASK, vb, 15);   // W[t][47]
        acc += v47;

        float sa = __shfl_up_sync(FULLMASK, va, 1);
        const float a31 = __shfl_sync(FULLMASK, va, 31);
        float sb = __shfl_up_sync(FULLMASK, vb, 1);
        if (l == 0) { sa = 0.0f; sb = a31; }

        va = fmaf(v47, pa, sa);
        vb = fmaf(v47, pb, sb);
    }
}

// ---------------------------------------------------------------------------
// Kernel 2: 2 series per thread, scalar FFMA.
//   Each LDS.128 of W[t..t+3][j-column... actually WT[j][4tq..4tq+3] feeds
//   8 FFMAs (2 series x 4 t) -> smem cyc/SM ~56k vs fma ~112k: fma-bound.
//   logvar: block-contiguous coalesced fill (this block's 192 rows).
// ---------------------------------------------------------------------------
__global__ void __launch_bounds__(TPB, 5)
forecast_kernel(const float* __restrict__ enc_l,
                const float* __restrict__ sigma_p,
                const float* __restrict__ ls2_p,
                float* __restrict__ out,
                int B) {
    __shared__ float sWT[AR_P * TLEN];   // 31.5 KB
    __shared__ float sd[TLEN];

    const int tid = threadIdx.x;
    {
        const float4* src4 = reinterpret_cast<const float4*>(g_WT);
        float4* dst4 = reinterpret_cast<float4*>(sWT);
        for (int i = tid; i < (AR_P * TLEN) / 4; i += TPB) dst4[i] = src4[i];
        for (int i = tid; i < TLEN; i += TPB) sd[i] = g_d[i];
    }
    __syncthreads();

    // ---- logvar: fully coalesced fill of this block's contiguous region ----
    const int base_s = blockIdx.x * SPB;
    const int nser = min(SPB, B - base_s);
    {
        const float L = ls2_p[0] + 2.0f * logf(sigma_p[0]);
        float4 Lv; Lv.x = L; Lv.y = L; Lv.z = L; Lv.w = L;
        float4* dst = reinterpret_cast<float4*>(
            out + (size_t)B * TLEN + (size_t)base_s * TLEN);
        const int n4 = nser * (TLEN / 4);
        for (int i = tid; i < n4; i += TPB) dst[i] = Lv;
    }

    const int sA = base_s + tid * SPT;     // this thread's series pair
    if (sA >= B) return;
    const int sB = sA + 1;

    // register-resident states: last 48 raw history values per series
    float yA[AR_P], yB[AR_P];
    {
        const float4* pA = reinterpret_cast<const float4*>(
            enc_l + (size_t)sA * HIST + (HIST - AR_P));
        const float4* pB = reinterpret_cast<const float4*>(
            enc_l + (size_t)sB * HIST + (HIST - AR_P));
#pragma unroll
        for (int q = 0; q < AR_P / 4; ++q) {
            const float4 a = pA[q];
            const float4 b = pB[q];
            yA[4 * q + 0] = a.x; yA[4 * q + 1] = a.y;
            yA[4 * q + 2] = a.z; yA[4 * q + 3] = a.w;
            yB[4 * q + 0] = b.x; yB[4 * q + 1] = b.y;
            yB[4 * q + 2] = b.z; yB[4 * q + 3] = b.w;
        }
    }

    float* rowA = out + (size_t)sA * TLEN;
    float* rowB = out + (size_t)sB * TLEN;

#pragma unroll 1
    for (int tq = 0; tq < TLEN / 4; ++tq) {
        const float4 d4 = *reinterpret_cast<const float4*>(sd + 4 * tq);
        float a0 = d4.x, a1 = d4.y, a2 = d4.z, a3 = d4.w;
        float b0 = d4.x, b1 = d4.y, b2 = d4.z, b3 = d4.w;

#pragma unroll
        for (int j = 0; j < AR_P; ++j) {
            // broadcast LDS.128: W[4tq..4tq+3][j] (t-contiguous in WT layout)
            const float4 w = *reinterpret_cast<const float4*>(
                sWT + j * TLEN + 4 * tq);
            const float ya = yA[j];
            const float yb = yB[j];
            a0 = fmaf(w.x, ya, a0);
            a1 = fmaf(w.y, ya, a1);
            a2 = fmaf(w.z, ya, a2);
            a3 = fmaf(w.w, ya, a3);
            b0 = fmaf(w.x, yb, b0);
            b1 = fmaf(w.y, yb, b1);
            b2 = fmaf(w.z, yb, b2);
            b3 = fmaf(w.w, yb, b3);
        }

        float4 oa; oa.x = a0; oa.y = a1; oa.z = a2; oa.w = a3;
        float4 ob; ob.x = b0; ob.y = b1; ob.z = b2; ob.w = b3;
        *reinterpret_cast<float4*>(rowA + 4 * tq) = oa;
        *reinterpret_cast<float4*>(rowB + 4 * tq) = ob;
    }
}

// ---------------------------------------------------------------------------
extern "C" void kernel_launch(void* const* d_in, const int* in_sizes, int n_in,
                              void* d_out, int out_size) {
    // inputs: enc_l, enc_t, enc_w, enc_s, phi, bias, log_sigma2, mu, sigma
    const float* enc_l = (const float*)d_in[0];
    const float* phi   = (const float*)d_in[4];
    const float* bias  = (const float*)d_in[5];
    const float* ls2   = (const float*)d_in[6];
    const float* mu    = (const float*)d_in[7];
    const float* sigma = (const float*)d_in[8];
    float* out = (float*)d_out;

    const int B = in_sizes[0] / HIST;   // enc_l is (B, HIST, 1)

    build_w_kernel<<<1, 32>>>(phi, bias, mu, sigma);

    const int blocks = (B + SPB - 1) / SPB;   // 683 -> single wave at 5 CTAs/SM
    forecast_kernel<<<blocks, TPB>>>(enc_l, sigma, ls2, out, B);
}

// round 9
// speedup vs baseline: 1.7773x; 1.0103x over previous
#include <cuda_runtime.h>
#include <cstdint>

#define FULLMASK 0xFFFFFFFFu
#define AR_P    48
#define TLEN    168          // forecast length
#define HIST    336
#define TPB     96
#define SPT     2            // series per thread (register-resident states)
#define SPB     (TPB * SPT)  // 192 series per block

// W transposed: g_WT[j*TLEN + t] = W[t][j]
// g_d[t] = mu*(1 - rowsum_t) + sigma*c_t   (affine offset: out_t = W[t]·y + d_t)
__device__ float g_WT[AR_P * TLEN];
__device__ float g_d[TLEN];

// ---------------------------------------------------------------------------
// Kernel 1: one warp builds WT and d via the companion rank-1 shift recursion:
//   W[0] = phi;  W[t][j] = W[t-1][j-1] + W[t-1][47]*phi[j]
//   c[t] = bias * (1 + sum_{u<t} W[u][47])
//   d[t] = mu*(1 - sum_j W[t][j]) + sigma*c[t]
// ---------------------------------------------------------------------------
__global__ void build_w_kernel(const float* __restrict__ phi,
                               const float* __restrict__ bias,
                               const float* __restrict__ mu_p,
                               const float* __restrict__ sigma_p) {
    const int l = threadIdx.x;
    const float pa = phi[l];
    const float pb = (l < 16) ? phi[l + 32] : 0.0f;
    float va = pa;
    float vb = pb;
    const float b0 = bias[0];
    const float mu = mu_p[0];
    const float sigma = sigma_p[0];
    float acc = 1.0f;

    for (int t = 0; t < TLEN; ++t) {
        g_WT[l * TLEN + t] = va;
        if (l < 16) g_WT[(l + 32) * TLEN + t] = vb;

        float rs = va + ((l < 16) ? vb : 0.0f);
#pragma unroll
        for (int o = 16; o; o >>= 1) rs += __shfl_xor_sync(FULLMASK, rs, o);
        if (l == 0) g_d[t] = mu * (1.0f - rs) + sigma * (b0 * acc);

        const float v47 = __shfl_sync(FULLMASK, vb, 15);   // W[t][47]
        acc += v47;

        float sa = __shfl_up_sync(FULLMASK, va, 1);
        const float a31 = __shfl_sync(FULLMASK, va, 31);
        float sb = __shfl_up_sync(FULLMASK, vb, 1);
        if (l == 0) { sa = 0.0f; sb = a31; }

        va = fmaf(v47, pa, sa);
        vb = fmaf(v47, pb, sb);
    }
}

// ---------------------------------------------------------------------------
// Kernel 2: 2 series per thread, scalar FFMA.
//   Each LDS.128 of W[t..t+3][j-column... actually WT[j][4tq..4tq+3] feeds
//   8 FFMAs (2 series x 4 t) -> smem cyc/SM ~56k vs fma ~112k: fma-bound.
//   logvar: block-contiguous coalesced fill (this block's 192 rows).
// ---------------------------------------------------------------------------
__global__ void __launch_bounds__(TPB, 5)
forecast_kernel(const float* __restrict__ enc_l,
                const float* __restrict__ sigma_p,
                const float* __restrict__ ls2_p,
                float* __restrict__ out,
                int B) {
    __shared__ float sWT[AR_P * TLEN];   // 31.5 KB
    __shared__ float sd[TLEN];

    const int tid = threadIdx.x;
    {
        const float4* src4 = reinterpret_cast<const float4*>(g_WT);
        float4* dst4 = reinterpret_cast<float4*>(sWT);
        for (int i = tid; i < (AR_P * TLEN) / 4; i += TPB) dst4[i] = src4[i];
        for (int i = tid; i < TLEN; i += TPB) sd[i] = g_d[i];
    }
    __syncthreads();

    // ---- logvar: fully coalesced fill of this block's contiguous region ----
    const int base_s = blockIdx.x * SPB;
    const int nser = min(SPB, B - base_s);
    {
        const float L = ls2_p[0] + 2.0f * logf(sigma_p[0]);
        float4 Lv; Lv.x = L; Lv.y = L; Lv.z = L; Lv.w = L;
        float4* dst = reinterpret_cast<float4*>(
            out + (size_t)B * TLEN + (size_t)base_s * TLEN);
        const int n4 = nser * (TLEN / 4);
        for (int i = tid; i < n4; i += TPB) dst[i] = Lv;
    }

    const int sA = base_s + tid * SPT;     // this thread's series pair
    if (sA >= B) return;
    const int sB = sA + 1;

    // register-resident states: last 48 raw history values per series
    float yA[AR_P], yB[AR_P];
    {
        const float4* pA = reinterpret_cast<const float4*>(
            enc_l + (size_t)sA * HIST + (HIST - AR_P));
        const float4* pB = reinterpret_cast<const float4*>(
            enc_l + (size_t)sB * HIST + (HIST - AR_P));
#pragma unroll
        for (int q = 0; q < AR_P / 4; ++q) {
            const float4 a = pA[q];
            const float4 b = pB[q];
            yA[4 * q + 0] = a.x; yA[4 * q + 1] = a.y;
            yA[4 * q + 2] = a.z; yA[4 * q + 3] = a.w;
            yB[4 * q + 0] = b.x; yB[4 * q + 1] = b.y;
            yB[4 * q + 2] = b.z; yB[4 * q + 3] = b.w;
        }
    }

    float* rowA = out + (size_t)sA * TLEN;
    float* rowB = out + (size_t)sB * TLEN;

#pragma unroll 1
    for (int tq = 0; tq < TLEN / 4; ++tq) {
        const float4 d4 = *reinterpret_cast<const float4*>(sd + 4 * tq);
        float a0 = d4.x, a1 = d4.y, a2 = d4.z, a3 = d4.w;
        float b0 = d4.x, b1 = d4.y, b2 = d4.z, b3 = d4.w;

#pragma unroll
        for (int j = 0; j < AR_P; ++j) {
            // broadcast LDS.128: W[4tq..4tq+3][j] (t-contiguous in WT layout)
            const float4 w = *reinterpret_cast<const float4*>(
                sWT + j * TLEN + 4 * tq);
            const float ya = yA[j];
            const float yb = yB[j];
            a0 = fmaf(w.x, ya, a0);
            a1 = fmaf(w.y, ya, a1);
            a2 = fmaf(w.z, ya, a2);
            a3 = fmaf(w.w, ya, a3);
            b0 = fmaf(w.x, yb, b0);
            b1 = fmaf(w.y, yb, b1);
            b2 = fmaf(w.z, yb, b2);
            b3 = fmaf(w.w, yb, b3);
        }

        float4 oa; oa.x = a0; oa.y = a1; oa.z = a2; oa.w = a3;
        float4 ob; ob.x = b0; ob.y = b1; ob.z = b2; ob.w = b3;
        *reinterpret_cast<float4*>(rowA + 4 * tq) = oa;
        *reinterpret_cast<float4*>(rowB + 4 * tq) = ob;
    }
}

// ---------------------------------------------------------------------------
extern "C" void kernel_launch(void* const* d_in, const int* in_sizes, int n_in,
                              void* d_out, int out_size) {
    // inputs: enc_l, enc_t, enc_w, enc_s, phi, bias, log_sigma2, mu, sigma
    const float* enc_l = (const float*)d_in[0];
    const float* phi   = (const float*)d_in[4];
    const float* bias  = (const float*)d_in[5];
    const float* ls2   = (const float*)d_in[6];
    const float* mu    = (const float*)d_in[7];
    const float* sigma = (const float*)d_in[8];
    float* out = (float*)d_out;

    const int B = in_sizes[0] / HIST;   // enc_l is (B, HIST, 1)

    build_w_kernel<<<1, 32>>>(phi, bias, mu, sigma);

    const int blocks = (B + SPB - 1) / SPB;   // 683 -> single wave at 5 CTAs/SM
    forecast_kernel<<<blocks, TPB>>>(enc_l, sigma, ls2, out, B);
}